// round 15
// baseline (speedup 1.0000x reference)
#include <cuda_runtime.h>
#include <math.h>

#define Hd 512
#define SEQ 2048
#define NTAGS 81
#define START_TAG 79
#define STOP_TAG 80
#define NEGV -10000.0f
#define NCTA_DIR 64
#define REC_CTAS (2*NCTA_DIR)
#define NWARP_DIR (NCTA_DIR*8)   // 512 arrivals per step per direction

// ---------------- scratch (device globals: no allocation allowed) ----------
__device__ float g_X[SEQ][Hd];           // gathered embeddings
__device__ float g_hseq[2][SEQ][Hd];     // hidden states
__device__ unsigned g_cnt[2][SEQ];       // per-step arrival counters (512 each)
__device__ float g_feats[SEQ][NTAGS];
__device__ float g_fv2[SEQ][NTAGS];      // viterbi step_vars history

// ---------------- gather + counter reset (fused, graph-deterministic) ------
__global__ void gather_reset_kernel(const int* __restrict__ sentence,
                                    const float* __restrict__ emb) {
    int t = blockIdx.x;
    if (threadIdx.x < 2) g_cnt[threadIdx.x][t] = 0u;
    int idx = sentence[t];
    const float4* src = (const float4*)(emb + (size_t)idx * Hd);
    ((float4*)(g_X[t]))[threadIdx.x] = src[threadIdx.x];   // 128 * float4 = 512
}

// ---------------- low-level helpers ----------------------------------------
__device__ __forceinline__ unsigned ld_acq(const unsigned* p) {
    unsigned v;
    asm volatile("ld.acquire.gpu.global.u32 %0, [%1];" : "=r"(v) : "l"(p) : "memory");
    return v;
}
__device__ __forceinline__ void red_release(unsigned* p) {
    asm volatile("red.add.release.gpu.global.u32 [%0], 1;" :: "l"(p) : "memory");
}
__device__ __forceinline__ void st_cg(float* p, float v) {
    asm volatile("st.global.cg.f32 [%0], %1;" :: "l"(p), "f"(v) : "memory");
}
__device__ __forceinline__ float2 ldcg_f2(const float2* p) {
    float2 v;
    asm volatile("ld.global.cg.v2.f32 {%0,%1}, [%2];"
                 : "=f"(v.x), "=f"(v.y) : "l"(p) : "memory");
    return v;
}
__device__ __forceinline__ unsigned long long pack2(float lo, float hi) {
    unsigned long long r;
    asm("mov.b64 %0, {%1,%2};" : "=l"(r) : "f"(lo), "f"(hi));
    return r;
}
__device__ __forceinline__ void unpack2(unsigned long long v, float& lo, float& hi) {
    asm("mov.b64 {%0,%1}, %2;" : "=f"(lo), "=f"(hi) : "l"(v));
}
__device__ __forceinline__ void ffma2(unsigned long long& d,
                                      unsigned long long a, unsigned long long b) {
    asm("fma.rn.f32x2 %0, %1, %2, %3;" : "=l"(d) : "l"(a), "l"(b), "l"(d));
}

// ---------------- recurrent LSTM (persistent, barrier-free warps) ----------
__global__ __launch_bounds__(256, 1) void lstm_kernel(
    const float* __restrict__ h0, const float* __restrict__ c0,
    const float* __restrict__ Whh_f, const float* __restrict__ Whh_b,
    const float* __restrict__ Wih_f, const float* __restrict__ Wih_b,
    const float* __restrict__ bih_f, const float* __restrict__ bhh_f,
    const float* __restrict__ bih_b, const float* __restrict__ bhh_b) {
    int dir = (blockIdx.x >= NCTA_DIR) ? 1 : 0;
    int cta = blockIdx.x - dir * NCTA_DIR;
    const float* Whh = dir ? Whh_b : Whh_f;
    const float* Wih = dir ? Wih_b : Wih_f;
    const float* bih = dir ? bih_b : bih_f;
    const float* bhh = dir ? bhh_b : bhh_f;
    int warp = threadIdx.x >> 5, lane = threadIdx.x & 31;
    int unit = cta * 8 + warp;       // 8 warps, one hidden unit each

    // weights packed as f32x2 pairs: lane owns elements {k*64+2*lane, +1}
    unsigned long long wh0[8], wh1[8], wh2[8], wh3[8];
    unsigned long long wx0[8], wx1[8], wx2[8], wx3[8];
    {
        const float* r0 = Whh + (size_t)unit * Hd;
        const float* r1 = Whh + (size_t)(unit + Hd) * Hd;
        const float* r2 = Whh + (size_t)(unit + 2 * Hd) * Hd;
        const float* r3 = Whh + (size_t)(unit + 3 * Hd) * Hd;
        const float* q0 = Wih + (size_t)unit * Hd;
        const float* q1 = Wih + (size_t)(unit + Hd) * Hd;
        const float* q2 = Wih + (size_t)(unit + 2 * Hd) * Hd;
        const float* q3 = Wih + (size_t)(unit + 3 * Hd) * Hd;
#pragma unroll
        for (int k = 0; k < 8; k++) {
            float2 v;
            v = ((const float2*)(r0 + k * 64))[lane]; wh0[k] = pack2(v.x, v.y);
            v = ((const float2*)(r1 + k * 64))[lane]; wh1[k] = pack2(v.x, v.y);
            v = ((const float2*)(r2 + k * 64))[lane]; wh2[k] = pack2(v.x, v.y);
            v = ((const float2*)(r3 + k * 64))[lane]; wh3[k] = pack2(v.x, v.y);
            v = ((const float2*)(q0 + k * 64))[lane]; wx0[k] = pack2(v.x, v.y);
            v = ((const float2*)(q1 + k * 64))[lane]; wx1[k] = pack2(v.x, v.y);
            v = ((const float2*)(q2 + k * 64))[lane]; wx2[k] = pack2(v.x, v.y);
            v = ((const float2*)(q3 + k * 64))[lane]; wx3[k] = pack2(v.x, v.y);
        }
    }

    float bi0 = 0.f, bi1 = 0.f, bi2 = 0.f, bi3 = 0.f;
    float bh0 = 0.f, bh1 = 0.f, bh2 = 0.f, bh3 = 0.f;
    float c = 0.f;
    if (lane == 0) {
        bi0 = bih[unit];            bh0 = bhh[unit];
        bi1 = bih[unit + Hd];       bh1 = bhh[unit + Hd];
        bi2 = bih[unit + 2 * Hd];   bh2 = bhh[unit + 2 * Hd];
        bi3 = bih[unit + 3 * Hd];   bh3 = bhh[unit + 3 * Hd];
        c = c0[dir * Hd + unit];
    }

    for (int s = 0; s < SEQ; s++) {
        int t = dir ? (SEQ - 1 - s) : s;

        // ---- u = x_t · Wih rows (issued right after previous release:
        //      overlaps all CTAs' h stores / counter flight)
        unsigned long long ua0 = 0ull, ua1 = 0ull, ua2 = 0ull, ua3 = 0ull;
        {
            const float2* xp = (const float2*)&g_X[t][0];
#pragma unroll
            for (int k = 0; k < 8; k++) {
                float2 xv = __ldg(xp + k * 32 + lane);
                unsigned long long x2 = pack2(xv.x, xv.y);
                ffma2(ua0, x2, wx0[k]);
                ffma2(ua1, x2, wx1[k]);
                ffma2(ua2, x2, wx2[k]);
                ffma2(ua3, x2, wx3[k]);
            }
        }
        float u0, u1, u2, u3;
        {
            float lo, hi;
            unpack2(ua0, lo, hi); u0 = __fadd_rn(lo, hi);
            unpack2(ua1, lo, hi); u1 = __fadd_rn(lo, hi);
            unpack2(ua2, lo, hi); u2 = __fadd_rn(lo, hi);
            unpack2(ua3, lo, hi); u3 = __fadd_rn(lo, hi);
        }
#pragma unroll
        for (int off = 16; off > 0; off >>= 1) {
            u0 += __shfl_xor_sync(0xffffffffu, u0, off);
            u1 += __shfl_xor_sync(0xffffffffu, u1, off);
            u2 += __shfl_xor_sync(0xffffffffu, u2, off);
            u3 += __shfl_xor_sync(0xffffffffu, u3, off);
        }

        // ---- acquire h_{t-1}: per-warp spin + per-lane acquire (round-7 proven)
        const float2* hsrc2;
        if (s == 0) {
            hsrc2 = (const float2*)(h0 + dir * Hd);
        } else {
            int tp = dir ? t + 1 : t - 1;
            const unsigned* cp = &g_cnt[dir][tp];
            if (lane == 0) {
                while (ld_acq(cp) < NWARP_DIR) {}
            }
            __syncwarp();
            (void)ld_acq(cp);   // per-lane acquire: release-sequence of RMWs
            hsrc2 = (const float2*)&g_hseq[dir][tp][0];
        }

        // ---- a = h_{t-1} · Whh rows (h straight into registers, no SMEM)
        unsigned long long aa0 = 0ull, aa1 = 0ull, aa2 = 0ull, aa3 = 0ull;
#pragma unroll
        for (int k = 0; k < 8; k++) {
            float2 hv = ldcg_f2(hsrc2 + k * 32 + lane);
            unsigned long long h2p = pack2(hv.x, hv.y);
            ffma2(aa0, h2p, wh0[k]);
            ffma2(aa1, h2p, wh1[k]);
            ffma2(aa2, h2p, wh2[k]);
            ffma2(aa3, h2p, wh3[k]);
        }
        float a0, a1, a2, a3;
        {
            float lo, hi;
            unpack2(aa0, lo, hi); a0 = __fadd_rn(lo, hi);
            unpack2(aa1, lo, hi); a1 = __fadd_rn(lo, hi);
            unpack2(aa2, lo, hi); a2 = __fadd_rn(lo, hi);
            unpack2(aa3, lo, hi); a3 = __fadd_rn(lo, hi);
        }
#pragma unroll
        for (int off = 16; off > 0; off >>= 1) {
            a0 += __shfl_xor_sync(0xffffffffu, a0, off);
            a1 += __shfl_xor_sync(0xffffffffu, a1, off);
            a2 += __shfl_xor_sync(0xffffffffu, a2, off);
            a3 += __shfl_xor_sync(0xffffffffu, a3, off);
        }
        if (lane == 0) {
            // g = ((xW + hW) + bih) + bhh  -- reference add order, no FMA fusion
            float gi = __fadd_rn(__fadd_rn(__fadd_rn(u0, a0), bi0), bh0);
            float gf = __fadd_rn(__fadd_rn(__fadd_rn(u1, a1), bi1), bh1);
            float gg = __fadd_rn(__fadd_rn(__fadd_rn(u2, a2), bi2), bh2);
            float go = __fadd_rn(__fadd_rn(__fadd_rn(u3, a3), bi3), bh3);
            float i_ = 1.f / (1.f + expf(-gi));
            float f_ = 1.f / (1.f + expf(-gf));
            float o_ = 1.f / (1.f + expf(-go));
            c = __fadd_rn(__fmul_rn(f_, c), __fmul_rn(i_, tanhf(gg)));
            float h2 = __fmul_rn(o_, tanhf(c));
            st_cg(&g_hseq[dir][t][unit], h2);   // bypass L1
            red_release(&g_cnt[dir][t]);        // same-thread release: airtight
        }
        // no CTA barriers anywhere in the loop
    }
}

// ---------------- feats: concat(hf,hb) @ Wt^T + bt (fp32) -------------------
__global__ __launch_bounds__(256) void feats_kernel(const float* __restrict__ Wt,
                                                    const float* __restrict__ bt) {
    int t = blockIdx.x;
    __shared__ float hc[2 * Hd];
    int tid = threadIdx.x;
#pragma unroll
    for (int i = 0; i < 4; i++) {
        int j = tid + i * 256;
        hc[j] = (j < Hd) ? g_hseq[0][t][j] : g_hseq[1][t][j - Hd];
    }
    __syncthreads();
    int warp = tid >> 5, lane = tid & 31;
    for (int n = warp; n < NTAGS; n += 8) {
        const float* w = Wt + (size_t)n * 2 * Hd;
        float s = 0.f;
#pragma unroll
        for (int k = lane; k < 2 * Hd; k += 32) s += w[k] * hc[k];
#pragma unroll
        for (int off = 16; off > 0; off >>= 1) s += __shfl_xor_sync(0xffffffffu, s, off);
        if (lane == 0) g_feats[t][n] = __fadd_rn(s, bt[n]);
    }
}

// ---------------- viterbi: 2 threads/row, transitions in registers ---------
#define VNT 192

__global__ void viterbi_kernel(const float* __restrict__ trans, float* __restrict__ out,
                               int out_size) {
    __shared__ float trs[NTAGS * NTAGS];
    __shared__ float fv[2][96];
    __shared__ int sh_best[1];
    extern __shared__ unsigned char bp[];            // SEQ * NTAGS backpointers
    int tid = threadIdx.x;
    bool active = (tid < 2 * NTAGS);
    int row = tid >> 1; if (row > NTAGS - 1) row = NTAGS - 1;   // pad threads
    int half = tid & 1;
    int base = half * 41;

    for (int i = tid; i < NTAGS * NTAGS; i += VNT) trs[i] = trans[i];
    if (tid < 96) {
        fv[0][tid] = (tid == START_TAG) ? 0.f : NEGV;
        fv[1][tid] = NEGV;                            // pad slots stay NEGV
    }
    __syncthreads();

    // this thread's half-row of transitions lives in registers
    float trg[41];
#pragma unroll
    for (int k = 0; k < 41; k++) {
        int j = base + k;
        trg[k] = (j < NTAGS) ? trs[row * NTAGS + j] : -2.e38f;  // sentinel never wins
    }

    int cur = 0;
    for (int t = 0; t < SEQ; t++) {
        const float* f = fv[cur];
        float b0 = -3.4e38f, b1 = -3.4e38f, b2 = -3.4e38f, b3 = -3.4e38f;
        int i0 = 0, i1 = 1, i2 = 2, i3 = 3;
#pragma unroll
        for (int k = 0; k < 40; k += 4) {
            float v0 = __fadd_rn(f[base + k],     trg[k]);     if (v0 > b0) { b0 = v0; i0 = k; }
            float v1 = __fadd_rn(f[base + k + 1], trg[k + 1]); if (v1 > b1) { b1 = v1; i1 = k + 1; }
            float v2 = __fadd_rn(f[base + k + 2], trg[k + 2]); if (v2 > b2) { b2 = v2; i2 = k + 2; }
            float v3 = __fadd_rn(f[base + k + 3], trg[k + 3]); if (v3 > b3) { b3 = v3; i3 = k + 3; }
        }
        { float v = __fadd_rn(f[base + 40], trg[40]); if (v > b0) { b0 = v; i0 = 40; } }
        // merge 4 stripes, first-index tie-break
        float bb = b0; int bi = i0;
        if (b1 > bb || (b1 == bb && i1 < bi)) { bb = b1; bi = i1; }
        if (b2 > bb || (b2 == bb && i2 < bi)) { bb = b2; bi = i2; }
        if (b3 > bb || (b3 == bb && i3 < bi)) { bb = b3; bi = i3; }
        bi += base;
        // merge the two halves (half0 has smaller indices: other wins only if
        // strictly greater, or equal with smaller index)
        float ob = __shfl_xor_sync(0xffffffffu, bb, 1);
        int   oi = __shfl_xor_sync(0xffffffffu, bi, 1);
        if (ob > bb || (ob == bb && oi < bi)) { bb = ob; bi = oi; }

        if (active && half == 0) {
            float feat = g_feats[t][row];
            bp[t * NTAGS + row] = (unsigned char)bi;
            float nv = __fadd_rn(bb, feat);
            fv[cur ^ 1][row] = nv;
            g_fv2[t][row] = nv;
        }
        __syncthreads();
        cur ^= 1;
    }

    if (tid == 0) {
        const float* f = fv[cur];
        float best = -3.4e38f; int bi = 0;
        for (int i = 0; i < NTAGS; i++) {
            float v = __fadd_rn(f[i], trs[STOP_TAG * NTAGS + i]);
            if (v > best) { best = v; bi = i; }
        }
        if (out_size > 0) out[0] = best;       // path_score
        sh_best[0] = bi;
        int tag = bi;
        for (int t = SEQ - 1; t >= 0; t--) {   // backtrace in SMEM
            if (1 + t < out_size) out[1 + t] = (float)tag;
            tag = bp[t * NTAGS + tag];
        }
    }
    __syncthreads();
    int best = sh_best[0];
    for (int k = tid; k < SEQ; k += VNT) {
        int idx = 1 + SEQ + k;
        if (idx < out_size) out[idx] = g_fv2[SEQ - 1 - k][best];  // best_tag_score
    }
}

// ---------------- launch -----------------------------------------------------
extern "C" void kernel_launch(void* const* d_in, const int* in_sizes, int n_in,
                              void* d_out, int out_size) {
    const int*   sentence = (const int*)d_in[0];
    const float* h0    = (const float*)d_in[1];
    const float* c0    = (const float*)d_in[2];
    const float* emb   = (const float*)d_in[3];
    const float* Wih_f = (const float*)d_in[4];
    const float* Whh_f = (const float*)d_in[5];
    const float* bih_f = (const float*)d_in[6];
    const float* bhh_f = (const float*)d_in[7];
    const float* Wih_b = (const float*)d_in[8];
    const float* Whh_b = (const float*)d_in[9];
    const float* bih_b = (const float*)d_in[10];
    const float* bhh_b = (const float*)d_in[11];
    const float* Wt    = (const float*)d_in[12];
    const float* bt    = (const float*)d_in[13];
    const float* trans = (const float*)d_in[14];
    float* out = (float*)d_out;

    gather_reset_kernel<<<SEQ, 128>>>(sentence, emb);
    lstm_kernel<<<REC_CTAS, 256>>>(h0, c0, Whh_f, Whh_b, Wih_f, Wih_b,
                                   bih_f, bhh_f, bih_b, bhh_b);
    feats_kernel<<<SEQ, 256>>>(Wt, bt);
    cudaFuncSetAttribute(viterbi_kernel, cudaFuncAttributeMaxDynamicSharedMemorySize,
                         SEQ * NTAGS);
    viterbi_kernel<<<1, VNT, SEQ * NTAGS>>>(trans, out, out_size);
}